// round 2
// baseline (speedup 1.0000x reference)
#include <cuda_runtime.h>

#define RSQRT2 0.70710678118654752440f

// Apply U = [[p, q], [conj(q), -conj(p)]] on the qubit with bit-weight R.
template <int R>
__device__ __forceinline__ void apply_pq(float2* st, float2 p, float2 q) {
#pragma unroll
    for (int hi = 0; hi < 16; hi += 2 * R) {
#pragma unroll
        for (int lo = 0; lo < R; ++lo) {
            int n0 = hi + lo, n1 = n0 + R;
            float2 s0 = st[n0], s1 = st[n1];
            float nx0 = p.x * s0.x - p.y * s0.y + q.x * s1.x - q.y * s1.y;
            float ny0 = p.x * s0.y + p.y * s0.x + q.x * s1.y + q.y * s1.x;
            float nx1 = q.x * s0.x + q.y * s0.y - p.x * s1.x - p.y * s1.y;
            float ny1 = q.x * s0.y - q.y * s0.x - p.x * s1.y + p.y * s1.x;
            st[n0] = make_float2(nx0, ny0);
            st[n1] = make_float2(nx1, ny1);
        }
    }
}

// In-place left-multiply by Rz(phi) where g=(cos(phi/2), sin(phi/2)):
// row0 *= e^{-i phi/2}. Structure [[p,q],[q*,-p*]] is preserved.
__device__ __forceinline__ void rz_pq(float2& p, float2& q, float2 g) {
    float c = g.x, s = g.y;
    p = make_float2(c * p.x + s * p.y, c * p.y - s * p.x);
    q = make_float2(c * q.x + s * q.y, c * q.y - s * q.x);
}

// In-place left-multiply by Ry(phi), g=(cos(phi/2), sin(phi/2)):
// p' = c p - s q*, q' = c q + s p*.
__device__ __forceinline__ void ry_pq(float2& p, float2& q, float2 g) {
    float c = g.x, s = g.y;
    float px = c * p.x - s * q.x;
    float py = c * p.y + s * q.y;
    float qx = c * q.x + s * p.x;
    float qy = c * q.y - s * p.y;
    p = make_float2(px, py);
    q = make_float2(qx, qy);
}

__device__ __forceinline__ float2 cmul(float2 a, float2 b) {
    return make_float2(a.x * b.x - a.y * b.y, a.x * b.y + a.y * b.x);
}

// sincos of half a pixel value
__device__ __forceinline__ float2 scpix(const float* base, int off) {
    float v = __ldg(base + off);
    float s, c;
    __sincosf(0.5f * v, &s, &c);
    return make_float2(c, s);
}

__global__ __launch_bounds__(32) void multi_encoding_kernel(
    const float* __restrict__ x, const float* __restrict__ crz_t,
    const float* __restrict__ ry_t, const float* __restrict__ fc1w,
    const float* __restrict__ fc1b, const float* __restrict__ fc2w,
    const float* __restrict__ fc2b, float* __restrict__ out, int B) {
    int img = blockIdx.x * 32 + threadIdx.x;
    if (img >= B) return;
    const float* xi = x + (size_t)img * 784;

    // ---- per-thread constants ----
    float th = __ldg(crz_t);
    float cs1, sn1;
    sincosf(0.5f * th, &sn1, &cs1);
    float c2 = cs1 * cs1 - sn1 * sn1, s2 = 2.f * cs1 * sn1;   // theta
    float c4 = c2 * c2 - s2 * s2, s4 = 2.f * c2 * s2;          // 2*theta
    float2 pm1 = make_float2(cs1, -sn1);   // exp(-i theta/2)
    float2 pp1 = make_float2(cs1, sn1);    // exp(+i theta/2)
    float2 pm2 = make_float2(c2, -s2);     // exp(-i theta)
    float2 pp4 = make_float2(c4, s4);      // exp(+2i theta)

    float tr = __ldg(ry_t);
    float cr, sr;
    sincosf(0.5f * tr, &sr, &cr);
    // base matrix for steps >= 1: Hb = H * Ry(tr) = [[a1,b1],[b1,-a1]]
    float a1 = (cr + sr) * RSQRT2;
    float b1 = (cr - sr) * RSQRT2;
    // measurement operator Ry^T Z Ry = [[mc, -msf],[-msf, -mc]], msf = sin(tr)
    float mc = cr * cr - sr * sr;
    float ms2 = 4.f * cr * sr;  // 2*sin(tr)

    // state = |0000>
    float2 st[16];
#pragma unroll
    for (int n = 0; n < 16; n++) st[n] = make_float2(0.f, 0.f);
    st[0] = make_float2(1.f, 0.f);

    float acc[20];
#pragma unroll
    for (int j = 0; j < 20; j++) acc[j] = 0.f;

    // Base for step 0 is plain H (no folded Ry yet)
    float Ab = RSQRT2, Bb = RSQRT2;

    const float4* w4 = reinterpret_cast<const float4*>(fc1w);
    const float2 ID = make_float2(1.f, 0.f);

#pragma unroll 1
    for (int wi = 0; wi < 14; wi++) {
#pragma unroll 1
        for (int wj = 0; wj < 14; wj++) {
            const float* base = xi + (2 * wi) * 28 + 2 * wj;
            float2 g0, g1, g2, g3, g4, g5, g6, g7;
            float2 g8, g9, g10, g11, g12, g13, g14, g15;
            if (wi < 13) {
                if (wj < 13) {
                    // 4x4 window, slot k -> (k/4, k%4)
                    g0 = scpix(base, 0);   g1 = scpix(base, 1);
                    g2 = scpix(base, 2);   g3 = scpix(base, 3);
                    g4 = scpix(base, 28);  g5 = scpix(base, 29);
                    g6 = scpix(base, 30);  g7 = scpix(base, 31);
                    g8 = scpix(base, 56);  g9 = scpix(base, 57);
                    g10 = scpix(base, 58); g11 = scpix(base, 59);
                    g12 = scpix(base, 84); g13 = scpix(base, 85);
                    g14 = scpix(base, 86); g15 = scpix(base, 87);
                } else {
                    // h=4, w=2: slot k<8 -> (k/2, k%2); rest identity
                    g0 = scpix(base, 0);  g1 = scpix(base, 1);
                    g2 = scpix(base, 28); g3 = scpix(base, 29);
                    g4 = scpix(base, 56); g5 = scpix(base, 57);
                    g6 = scpix(base, 84); g7 = scpix(base, 85);
                    g8 = ID; g9 = ID; g10 = ID; g11 = ID;
                    g12 = ID; g13 = ID; g14 = ID; g15 = ID;
                }
            } else {
                if (wj < 13) {
                    // h=2, w=4: slot k<8 -> (k/4, k%4); rest identity
                    g0 = scpix(base, 0);  g1 = scpix(base, 1);
                    g2 = scpix(base, 2);  g3 = scpix(base, 3);
                    g4 = scpix(base, 28); g5 = scpix(base, 29);
                    g6 = scpix(base, 30); g7 = scpix(base, 31);
                    g8 = ID; g9 = ID; g10 = ID; g11 = ID;
                    g12 = ID; g13 = ID; g14 = ID; g15 = ID;
                } else {
                    // 2x2: slot k<4 -> (k/2, k%2); rest identity
                    g0 = scpix(base, 0);  g1 = scpix(base, 1);
                    g2 = scpix(base, 28); g3 = scpix(base, 29);
                    g4 = ID; g5 = ID; g6 = ID; g7 = ID;
                    g8 = ID; g9 = ID; g10 = ID; g11 = ID;
                    g12 = ID; g13 = ID; g14 = ID; g15 = ID;
                }
            }

            // Wire 0 (bit 8): U = Rz(g4)Ry(g3)Rz(g2)Ry(g1)Rz(g0)*Base
            {
                float2 p = make_float2(Ab, 0.f), q = make_float2(Bb, 0.f);
                rz_pq(p, q, g0); ry_pq(p, q, g1); rz_pq(p, q, g2);
                ry_pq(p, q, g3); rz_pq(p, q, g4);
                apply_pq<8>(st, p, q);
            }
            // Wire 1 (bit 4): slots 5..9
            {
                float2 p = make_float2(Ab, 0.f), q = make_float2(Bb, 0.f);
                rz_pq(p, q, g5); ry_pq(p, q, g6); rz_pq(p, q, g7);
                ry_pq(p, q, g8); rz_pq(p, q, g9);
                apply_pq<4>(st, p, q);
            }
            // Wire 2 (bit 2): slots 10..14
            {
                float2 p = make_float2(Ab, 0.f), q = make_float2(Bb, 0.f);
                rz_pq(p, q, g10); ry_pq(p, q, g11); rz_pq(p, q, g12);
                ry_pq(p, q, g13); rz_pq(p, q, g14);
                apply_pq<2>(st, p, q);
            }
            // Wire 3 (bit 1): U = Rz(g15)*Base
            {
                float2 p = make_float2(Ab * g15.x, -Ab * g15.y);
                float2 q = make_float2(Bb * g15.x, -Bb * g15.y);
                apply_pq<1>(st, p, q);
            }

            // CRZ ring diagonal (signs: 1,2,4,8:-1; 5,10:-2; 7,11,13,14:+1; 15:+4)
            st[1] = cmul(st[1], pm1);
            st[2] = cmul(st[2], pm1);
            st[4] = cmul(st[4], pm1);
            st[5] = cmul(st[5], pm2);
            st[7] = cmul(st[7], pp1);
            st[8] = cmul(st[8], pm1);
            st[10] = cmul(st[10], pm2);
            st[11] = cmul(st[11], pp1);
            st[13] = cmul(st[13], pp1);
            st[14] = cmul(st[14], pp1);
            st[15] = cmul(st[15], pp4);

            // Measurement with rotated operator (final Ry folded in):
            // feat_w = cos(tr)*sum(pr0-pr1) - 2 sin(tr)*sum Re(s0* s1)
            float pr[16];
#pragma unroll
            for (int n = 0; n < 16; n++)
                pr[n] = st[n].x * st[n].x + st[n].y * st[n].y;

            float d0 = 0.f, x0 = 0.f, d1 = 0.f, x1 = 0.f;
            float d2 = 0.f, x2 = 0.f, d3 = 0.f, x3 = 0.f;
#pragma unroll
            for (int n = 0; n < 8; n++) {
                int n1 = n + 8;
                d0 += pr[n] - pr[n1];
                x0 += st[n].x * st[n1].x + st[n].y * st[n1].y;
            }
#pragma unroll
            for (int m = 0; m < 8; m++) {
                int n = (m & 3) + ((m >> 2) << 3);  // 0..3, 8..11
                int n1 = n + 4;
                d1 += pr[n] - pr[n1];
                x1 += st[n].x * st[n1].x + st[n].y * st[n1].y;
            }
#pragma unroll
            for (int m = 0; m < 8; m++) {
                int n = (m & 1) + ((m >> 1) << 2);  // 0,1,4,5,8,9,12,13
                int n1 = n + 2;
                d2 += pr[n] - pr[n1];
                x2 += st[n].x * st[n1].x + st[n].y * st[n1].y;
            }
#pragma unroll
            for (int m = 0; m < 8; m++) {
                int n = m << 1;
                int n1 = n + 1;
                d3 += pr[n] - pr[n1];
                x3 += st[n].x * st[n1].x + st[n].y * st[n1].y;
            }
            float f0 = mc * d0 - ms2 * x0;
            float f1 = mc * d1 - ms2 * x1;
            float f2 = mc * d2 - ms2 * x2;
            float f3 = mc * d3 - ms2 * x3;

            // fc1 accumulation: columns [4*widx .. 4*widx+3]
            int widx = wi * 14 + wj;
#pragma unroll
            for (int jj = 0; jj < 20; jj++) {
                float4 wv = __ldg(&w4[jj * 196 + widx]);
                acc[jj] += f0 * wv.x + f1 * wv.y + f2 * wv.z + f3 * wv.w;
            }

            // After step 0, base becomes H*Ry(tr)
            Ab = a1;
            Bb = b1;
        }
    }

    // fc1 bias + leaky relu + fc2
    float o0 = __ldg(fc2b + 0);
    float o1 = __ldg(fc2b + 1);
#pragma unroll
    for (int jj = 0; jj < 20; jj++) {
        float v = acc[jj] + __ldg(fc1b + jj);
        v = v > 0.f ? v : 0.1f * v;
        o0 += v * __ldg(fc2w + jj);
        o1 += v * __ldg(fc2w + 20 + jj);
    }
    reinterpret_cast<float2*>(out)[img] = make_float2(o0, o1);
}

extern "C" void kernel_launch(void* const* d_in, const int* in_sizes, int n_in,
                              void* d_out, int out_size) {
    const float* x = (const float*)d_in[0];
    const float* crz_t = (const float*)d_in[1];
    const float* ry_t = (const float*)d_in[2];
    const float* fc1w = (const float*)d_in[3];
    const float* fc1b = (const float*)d_in[4];
    const float* fc2w = (const float*)d_in[5];
    const float* fc2b = (const float*)d_in[6];
    float* out = (float*)d_out;

    int B = in_sizes[0] / 784;
    int grid = (B + 31) / 32;
    multi_encoding_kernel<<<grid, 32>>>(x, crz_t, ry_t, fc1w, fc1b, fc2w, fc2b,
                                        out, B);
}